// round 14
// baseline (speedup 1.0000x reference)
#include <cuda_runtime.h>

#define T_TOKENS 16384
#define HID      2048
#define NEXP     128
#define NCOL     256      // full logits [0,128) + bvh logits [128,256)
#define NCAND    32
#define TK       8

#define BM   32
#define BK   16
#define NTH  256
#define AST  36           // As row stride (floats): 36*4=144B, 16B-aligned rows
#define BST  260          // Bs row stride (floats): 1040B, 16B-aligned rows
#define NKIT (HID / BK)   // 128 k-steps

#define OFFV ((size_t)T_TOKENS * NEXP)
#define OFFI (OFFV + (size_t)T_TOKENS * TK)

typedef unsigned long long ull;

// 16 MB logits scratch (static __device__ global, no allocation)
__device__ float g_logits[(size_t)T_TOKENS * NCOL];

// ---- packed f32x2 helpers (Blackwell: 2 fp32 ops per instruction) ----
__device__ __forceinline__ ull pk2(float lo, float hi) {
    ull r;
    asm("mov.b64 %0, {%1, %2};" : "=l"(r)
        : "r"(__float_as_uint(lo)), "r"(__float_as_uint(hi)));
    return r;
}
__device__ __forceinline__ void fma2(ull& c, ull a, ull b) {
    asm("fma.rn.f32x2 %0, %1, %2, %0;" : "+l"(c) : "l"(a), "l"(b));
}
__device__ __forceinline__ ull add2(ull a, ull b) {
    ull r; asm("add.rn.f32x2 %0, %1, %2;" : "=l"(r) : "l"(a), "l"(b)); return r;
}
__device__ __forceinline__ ull sub2(ull a, ull b) {
    ull r; asm("sub.rn.f32x2 %0, %1, %2;" : "=l"(r) : "l"(a), "l"(b)); return r;
}
__device__ __forceinline__ float2 upk2(ull v) {
    unsigned lo, hi;
    asm("mov.b64 {%0, %1}, %2;" : "=r"(lo), "=r"(hi) : "l"(v));
    return make_float2(__uint_as_float(lo), __uint_as_float(hi));
}

// monotone key for float ordering
__device__ __forceinline__ unsigned monok(float x) {
    unsigned u = __float_as_uint(x);
    return (u & 0x80000000u) ? ~u : (u | 0x80000000u);
}

__device__ __forceinline__ float wmax(float v) {
#pragma unroll
    for (int o = 16; o > 0; o >>= 1) v = fmaxf(v, __shfl_xor_sync(0xffffffffu, v, o));
    return v;
}
__device__ __forceinline__ float wsum(float v) {
#pragma unroll
    for (int o = 16; o > 0; o >>= 1) v += __shfl_xor_sync(0xffffffffu, v, o);
    return v;
}
__device__ __forceinline__ ull wmaxu(ull v) {
#pragma unroll
    for (int o = 16; o > 0; o >>= 1) {
        ull t = __shfl_xor_sync(0xffffffffu, v, o);
        v = (t > v) ? t : v;
    }
    return v;
}

// -------- selection with exact lax.top_k tie semantics (lowest index) --------
// Lane l holds probs for experts l, l+32, l+64, l+96 (full p*, bvh q*).
__device__ __forceinline__ void run_select(
    int tok, int l,
    float p0, float p1, float p2, float p3,
    float q0, float q1, float q2, float q3,
    float* __restrict__ out)
{
    const unsigned FULL = 0xffffffffu;

    // stage 1: top-32 of bvh probs; tie -> lowest expert id
    ull k0 = ((ull)monok(q0) << 32) | (unsigned)(127 - l);
    ull k1 = ((ull)monok(q1) << 32) | (unsigned)(95 - l);
    ull k2 = ((ull)monok(q2) << 32) | (unsigned)(63 - l);
    ull k3 = ((ull)monok(q3) << 32) | (unsigned)(31 - l);
    int my_cand = 0;
#pragma unroll 1
    for (int c = 0; c < NCAND; ++c) {
        ull loc  = (k0 > k1) ? k0 : k1;
        ull loc2 = (k2 > k3) ? k2 : k3;
        loc = (loc > loc2) ? loc : loc2;
        ull best = wmaxu(loc);
        int id = 127 - (int)(unsigned)(best & 0xffffffffu);
        if (l == c) my_cand = id;
        if ((id & 31) == l) {
            int slot = id >> 5;
            if      (slot == 0) k0 = 0;
            else if (slot == 1) k1 = 0;
            else if (slot == 2) k2 = 0;
            else                k3 = 0;
        }
    }

    // gather full prob of my candidate
    int srcl = my_cand & 31, slot = my_cand >> 5;
    float v0 = __shfl_sync(FULL, p0, srcl);
    float v1 = __shfl_sync(FULL, p1, srcl);
    float v2 = __shfl_sync(FULL, p2, srcl);
    float v3 = __shfl_sync(FULL, p3, srcl);
    float cp = (slot == 0) ? v0 : (slot == 1) ? v1 : (slot == 2) ? v2 : v3;

    // stage 2: top-8 among 32 candidates; tie -> lowest candidate position
    ull mykey = ((ull)monok(cp) << 32) | (unsigned)(31 - l);
    float rv = 0.0f; int ri = 0;
#pragma unroll 1
    for (int r = 0; r < TK; ++r) {
        ull best = wmaxu(mykey);
        int cw = 31 - (int)(unsigned)(best & 0xffffffffu);
        float wv = __shfl_sync(FULL, cp, cw);
        int   wi = __shfl_sync(FULL, my_cand, cw);
        if (l == r)  { rv = wv; ri = wi; }
        if (l == cw) mykey = 0;
    }

    float ssum = wsum(rv);   // lanes >= 8 contribute 0
    if (l < TK) {
        out[OFFV + (size_t)tok * TK + l] = rv / ssum;
        out[OFFI + (size_t)tok * TK + l] = (float)ri;
    }
}

// ====== fused GEMM (blocked-Kahan, sigma ~1.7e-7) + softmax + top-k ======
__global__ __launch_bounds__(NTH)
void router_kernel(const float* __restrict__ X,
                   const float* __restrict__ Wo,
                   const float* __restrict__ Wb,
                   float* __restrict__ out)
{
    __shared__ float As[2][BK][AST];   //  4608 B
    __shared__ float Bs[2][BK][BST];   // 33280 B

    const int tid = threadIdx.x;
    const int m0  = blockIdx.x * BM;

    // compute mapping: 8 tokens x 4 experts per thread
    const int eg = tid & 63;    // expert group: cols 4*eg .. 4*eg+3
    const int tg = tid >> 6;    // token group:  rows 8*tg .. 8*tg+7

    // loaders: A by first 128 threads (32 rows x 4 float4), B by all (4 rows each)
    const bool aload = (tid < 128);
    const int  xr = tid >> 2;        // A row (0..31) when aload
    const int  xc = tid & 3;         // float4 column within BK
    const int  br = tid >> 2;        // B row base (0..63)

    const float4* xsrc = aload
        ? reinterpret_cast<const float4*>(X + (size_t)(m0 + xr) * HID) + xc
        : reinterpret_cast<const float4*>(X);
    const float4* wsrc[4];
#pragma unroll
    for (int s = 0; s < 4; ++s) {
        int wr = br + 64 * s;   // 0..255 : [0,128)->Wo, [128,256)->Wb
        const float* base = (wr < NEXP) ? (Wo + (size_t)wr * HID)
                                        : (Wb + (size_t)(wr - NEXP) * HID);
        wsrc[s] = reinterpret_cast<const float4*>(base) + xc;
    }

    auto stash = [&](int b, float4 vx, float4 w0, float4 w1, float4 w2, float4 w3) {
        int c0 = xc * 4;
        if (aload) {
            As[b][c0+0][xr] = vx.x; As[b][c0+1][xr] = vx.y;
            As[b][c0+2][xr] = vx.z; As[b][c0+3][xr] = vx.w;
        }
        Bs[b][c0+0][br      ] = w0.x; Bs[b][c0+1][br      ] = w0.y;
        Bs[b][c0+2][br      ] = w0.z; Bs[b][c0+3][br      ] = w0.w;
        Bs[b][c0+0][br + 64 ] = w1.x; Bs[b][c0+1][br + 64 ] = w1.y;
        Bs[b][c0+2][br + 64 ] = w1.z; Bs[b][c0+3][br + 64 ] = w1.w;
        Bs[b][c0+0][br + 128] = w2.x; Bs[b][c0+1][br + 128] = w2.y;
        Bs[b][c0+2][br + 128] = w2.z; Bs[b][c0+3][br + 128] = w2.w;
        Bs[b][c0+0][br + 192] = w3.x; Bs[b][c0+1][br + 192] = w3.y;
        Bs[b][c0+2][br + 192] = w3.z; Bs[b][c0+3][br + 192] = w3.w;
    };

    // main accumulators + Kahan compensation (nc = minus the compensation)
    ull acc[8][2], nc[8][2];
#pragma unroll
    for (int t = 0; t < 8; ++t) {
        acc[t][0] = 0ull; acc[t][1] = 0ull;
        nc[t][0]  = 0ull; nc[t][1]  = 0ull;
    }

    // preload + stash stage 0
    {
        float4 vx = make_float4(0.f,0.f,0.f,0.f);
        if (aload) vx = xsrc[0];
        float4 w0 = wsrc[0][0], w1 = wsrc[1][0], w2 = wsrc[2][0], w3 = wsrc[3][0];
        stash(0, vx, w0, w1, w2, w3);
    }
    __syncthreads();

    int buf = 0;
    for (int kt = 0; kt < NKIT; ++kt) {
        float4 nx = make_float4(0.f,0.f,0.f,0.f), nw0, nw1, nw2, nw3;
        if (kt + 1 < NKIT) {
            int off = (kt + 1) * (BK / 4);
            if (aload) nx = xsrc[off];
            nw0 = wsrc[0][off]; nw1 = wsrc[1][off];
            nw2 = wsrc[2][off]; nw3 = wsrc[3][off];
        }

        // per-tile partial accumulator (16 serial products)
        ull blk[8][2];
#pragma unroll
        for (int t = 0; t < 8; ++t) { blk[t][0] = 0ull; blk[t][1] = 0ull; }

        const float* Ab = &As[buf][0][tg * 8];
        const float* Bb = &Bs[buf][0][eg * 4];
#pragma unroll
        for (int kk = 0; kk < BK; ++kk) {
            float4 a0 = *(const float4*)(Ab + kk * AST);
            float4 a1 = *(const float4*)(Ab + kk * AST + 4);
            float4 bb = *(const float4*)(Bb + kk * BST);
            ull bp0 = pk2(bb.x, bb.y);
            ull bp1 = pk2(bb.z, bb.w);
            float av[8] = {a0.x,a0.y,a0.z,a0.w, a1.x,a1.y,a1.z,a1.w};
#pragma unroll
            for (int t = 0; t < 8; ++t) {
                ull ap = pk2(av[t], av[t]);
                fma2(blk[t][0], ap, bp0);
                fma2(blk[t][1], ap, bp1);
            }
        }

        // Kahan fold: acc += blk with compensation
#pragma unroll
        for (int t = 0; t < 8; ++t) {
#pragma unroll
            for (int j = 0; j < 2; ++j) {
                ull y  = add2(blk[t][j], nc[t][j]);
                ull tt = add2(acc[t][j], y);
                ull d  = sub2(tt, acc[t][j]);
                nc[t][j] = sub2(y, d);
                acc[t][j] = tt;
            }
        }

        if (kt + 1 < NKIT) {
            __syncthreads();
            stash(buf ^ 1, nx, nw0, nw1, nw2, nw3);
            __syncthreads();
            buf ^= 1;
        }
    }

    // add back compensation, write logits tile to global scratch
#pragma unroll
    for (int t = 0; t < 8; ++t) {
        int m = tg * 8 + t;
        float2 c0 = upk2(add2(acc[t][0], nc[t][0]));
        float2 c1 = upk2(add2(acc[t][1], nc[t][1]));
        float4 v = make_float4(c0.x, c0.y, c1.x, c1.y);
        *reinterpret_cast<float4*>(g_logits + (size_t)(m0 + m) * NCOL + eg * 4) = v;
    }
    __syncthreads();   // block-scope visibility of global writes

    // ---------------- epilogue: one warp per token, 4 tokens/warp ----------------
    const int l    = tid & 31;
    const int warp = tid >> 5;

#pragma unroll 1
    for (int i = 0; i < 4; ++i) {
        const int tok = m0 + warp * 4 + i;
        const float* row = g_logits + (size_t)tok * NCOL;

        float f0 = row[l], f1 = row[l + 32], f2 = row[l + 64], f3 = row[l + 96];
        float g0 = row[128 + l], g1 = row[160 + l], g2 = row[192 + l], g3 = row[224 + l];

        // full softmax (jax: exp(x - max) / sum)
        float mx  = wmax(fmaxf(fmaxf(f0, f1), fmaxf(f2, f3)));
        float e0 = expf(f0 - mx), e1 = expf(f1 - mx), e2 = expf(f2 - mx), e3 = expf(f3 - mx);
        float inv = 1.0f / wsum(e0 + e1 + e2 + e3);
        float p0 = e0 * inv, p1 = e1 * inv, p2 = e2 * inv, p3 = e3 * inv;
        {
            float* po = out + (size_t)tok * NEXP;
            po[l] = p0; po[l + 32] = p1; po[l + 64] = p2; po[l + 96] = p3;
        }

        // bvh softmax
        float bmx = wmax(fmaxf(fmaxf(g0, g1), fmaxf(g2, g3)));
        float q0 = expf(g0 - bmx), q1 = expf(g1 - bmx), q2 = expf(g2 - bmx), q3 = expf(g3 - bmx);
        float binv = 1.0f / wsum(q0 + q1 + q2 + q3);
        q0 *= binv; q1 *= binv; q2 *= binv; q3 *= binv;

        run_select(tok, l, p0, p1, p2, p3, q0, q1, q2, q3, out);
    }
}

extern "C" void kernel_launch(void* const* d_in, const int* in_sizes, int n_in,
                              void* d_out, int out_size) {
    (void)in_sizes; (void)n_in; (void)out_size;
    const float* X  = (const float*)d_in[0];
    const float* Wo = (const float*)d_in[1];
    const float* Wb = (const float*)d_in[2];
    router_kernel<<<T_TOKENS / BM, NTH>>>(X, Wo, Wb, (float*)d_out);
}